// round 7
// baseline (speedup 1.0000x reference)
#include <cuda_runtime.h>
#include <math.h>

#define D_MODEL   64
#define SEQ       4096
#define BATCH_N   256
#define VOCAB     50257
#define LUT_N     4096
#define PF        8

#define TWOPI_F   6.2831853071795864769f
#define PHI_F     1.6180339887498948482f
#define STEP_F    ((float)(6.283185307179586 / 4096.0))
#define KSCALE    651.8986469044033f          /* 4096 / (2*pi) */
#define MAGIC     12582912.0f                 /* 2^23 + 2^22 : round-down int extractor */

// Precomputed per-(token, d): (KSCALE/(1+|w|), b*KSCALE), interleaved for LDG.64
__device__ float2 g_A[(size_t)VOCAB * D_MODEL];

__global__ void __launch_bounds__(256)
prep_kernel(const float* __restrict__ emb)
{
    int idx = blockIdx.x * 256 + threadIdx.x;
    if (idx >= VOCAB * D_MODEL) return;
    int tok = idx >> 6;
    int d   = idx & 63;
    float w = emb[(size_t)tok * 128 + d];
    float b = emb[(size_t)tok * 128 + 64 + d];
    float a = __fdividef(KSCALE, __fadd_rn(1.0f, fabsf(w)));
    g_A[idx] = make_float2(a, __fmul_rn(b, KSCALE));
}

// smem: lut 32KB | s_step[2][4096] int2 64KB | h[2][128] 1KB
#define SM_LUT_OFF   0
#define SM_STEP_OFF  32768
#define SM_H_OFF     98304
#define SM_TOTAL     99328

__global__ void __launch_bounds__(128, 1)
rin_scan_kernel(const int* __restrict__ ids,
                const float* __restrict__ projW,
                const float* __restrict__ projB,
                float* __restrict__ out)
{
    extern __shared__ unsigned char smem[];
    float2* s_lut  = (float2*)(smem + SM_LUT_OFF);
    int2*   s_step = (int2*)  (smem + SM_STEP_OFF);   // [2][4096]: (tok*512, f32bits(tphi*K))
    float*  s_h    = (float*) (smem + SM_H_OFF);      // [2][128]

    const int tid = threadIdx.x;
    const int sub = tid >> 6;
    const int d   = tid & 63;
    const int batch = blockIdx.x * 2 + sub;

    // ---- init: LUT ----
    for (int i = tid; i < LUT_N; i += 128) {
        float ang = __fmul_rn(STEP_F, (float)i);
        s_lut[i] = make_float2(sinf(ang), cosf(ang));   // (sin, cos)
    }
    // ---- init: per-step merged (token byte-offset, tphi*K) ----
    {
        const int* row = ids + (size_t)batch * SEQ;
        int2* st = s_step + sub * SEQ;
        for (int i = d; i < SEQ; i += 64) {
            int tok = row[i];
            float tphiK = __fmul_rn(fmodf(__fmul_rn((float)i, PHI_F), TWOPI_F), KSCALE);
            st[i] = make_int2(tok * 512, __float_as_int(tphiK));
        }
    }
    __syncthreads();

    const int2* st = s_step + sub * SEQ;
    const char* gA = (const char*)g_A;
    const int d8 = d * 8;

    // ---- prologue: prefetch first PF steps ----
    float2 pf[PF];
    float  tph[PF];
#pragma unroll
    for (int j = 0; j < PF; j++) {
        int2 e = st[j];
        tph[j] = __int_as_float(e.y);
        pf[j]  = __ldg((const float2*)(gA + e.x + d8));
    }

    float hr = 0.0f, hi = 0.0f;   // h = (cos, sin) of tracked phase

    for (int sb = 0; sb < SEQ; sb += PF) {
#pragma unroll
        for (int j = 0; j < PF; j++) {
            const int s = sb + j;
            const float a    = pf[j].x;
            const float bk   = pf[j].y;
            const float tphi = tph[j];

            // prefetch step s+PF (wraps harmlessly on the final chunk)
            {
                int2 e = st[(s + PF) & (SEQ - 1)];
                tph[j] = __int_as_float(e.y);
                pf[j]  = __ldg((const float2*)(gA + e.x + d8));
            }

            float c = __fadd_rn(bk, tphi);             // off critical path

            // ---- critical path ----
            float yr = __fmaf_rn(hr, a, c);
            float yi = __fmaf_rn(hi, a, c);
            int   br3 = __float_as_int(__fadd_rd(yr, MAGIC)) << 3;   // parallel shifts
            int   bi3 = __float_as_int(__fadd_rd(yi, MAGIC)) << 3;
            int   addr = (br3 + bi3) & 0x7FF8;         // ((br+bi)&4095)*8, exact

            float2 sc = *(const float2*)((const char*)s_lut + addr);
            hi = sc.x;                                 // sin
            hr = sc.y;                                 // cos
        }
    }

    // ---- projection: out[b,n] = sum_k h[k]*W[n,k] + bias[n] ----
    float* sh = s_h + sub * 128;
    sh[d] = hr;
    sh[64 + d] = hi;
    __syncthreads();

    float acc0 = 0.0f, acc1 = 0.0f;
    const float* w0 = projW + (size_t)d * 128;
    const float* w1 = projW + (size_t)(d + 64) * 128;
#pragma unroll 8
    for (int kk = 0; kk < 128; kk++) {
        float hk = sh[kk];
        acc0 = __fmaf_rn(hk, __ldg(w0 + kk), acc0);
        acc1 = __fmaf_rn(hk, __ldg(w1 + kk), acc1);
    }
    out[(size_t)batch * 128 + d]      = __fadd_rn(acc0, __ldg(projB + d));
    out[(size_t)batch * 128 + 64 + d] = __fadd_rn(acc1, __ldg(projB + d + 64));
}

extern "C" void kernel_launch(void* const* d_in, const int* in_sizes, int n_in,
                              void* d_out, int out_size)
{
    const int*   ids  = (const int*)d_in[0];     // (256, 4096) int32
    const float* emb  = (const float*)d_in[1];   // (50257, 128) f32
    const float* W    = (const float*)d_in[2];   // (128, 128) f32
    const float* bias = (const float*)d_in[3];   // (128,) f32
    float* out = (float*)d_out;                  // (256, 128) f32

    prep_kernel<<<(VOCAB * D_MODEL + 255) / 256, 256>>>(emb);

    cudaFuncSetAttribute(rin_scan_kernel,
                         cudaFuncAttributeMaxDynamicSharedMemorySize, SM_TOTAL);
    rin_scan_kernel<<<BATCH_N / 2, 128, SM_TOTAL>>>(ids, W, bias, out);
}

// round 9
// speedup vs baseline: 1.5352x; 1.5352x over previous
#include <cuda_runtime.h>
#include <math.h>

#define D_MODEL   64
#define SEQ       4096
#define BATCH_N   256
#define VOCAB     50257
#define PF        8

#define TWOPI_F   6.2831853071795864769f
#define PHI_F     1.6180339887498948482f
#define STEP_F    ((float)(6.283185307179586 / 4096.0))   /* table angle step */
#define KSCALE    651.8986469044033f                      /* 4096 / (2*pi) */
#define MAGIC     12582912.0f                             /* 2^23 + 2^22 */
#define MAGIC_I   0x4B400000                              /* bit pattern of MAGIC */

// Precomputed per-(token, d): (KSCALE/(1+|w|), b*KSCALE), interleaved for LDG.64
__device__ float2 g_A[(size_t)VOCAB * D_MODEL];

__global__ void __launch_bounds__(256)
prep_kernel(const float* __restrict__ emb)
{
    int idx = blockIdx.x * 256 + threadIdx.x;
    if (idx >= VOCAB * D_MODEL) return;
    int tok = idx >> 6;
    int d   = idx & 63;
    float w = emb[(size_t)tok * 128 + d];
    float b = emb[(size_t)tok * 128 + 64 + d];
    float a = __fdividef(KSCALE, __fadd_rn(1.0f, fabsf(w)));
    g_A[idx] = make_float2(a, __fmul_rn(b, KSCALE));
}

// smem: tok[2][4096] 32KB | tphiK[4096] 16KB | h[2][128] 1KB
#define SM_TOK_OFF   0
#define SM_TPHI_OFF  32768
#define SM_H_OFF     49152
#define SM_TOTAL     50176

__global__ void __launch_bounds__(128, 1)
rin_scan_kernel(const int* __restrict__ ids,
                const float* __restrict__ projW,
                const float* __restrict__ projB,
                float* __restrict__ out)
{
    extern __shared__ unsigned char smem[];
    int*    s_tok   = (int*)  (smem + SM_TOK_OFF);    // [2][4096]
    float*  s_tphiK = (float*)(smem + SM_TPHI_OFF);   // [4096], shared by both subs
    float*  s_h     = (float*)(smem + SM_H_OFF);      // [2][128]

    const int tid = threadIdx.x;
    const int sub = tid >> 6;
    const int d   = tid & 63;
    const int batch = blockIdx.x * 2 + sub;

    // ---- init ----
    for (int i = tid; i < SEQ; i += 128) {
        s_tphiK[i] = __fmul_rn(fmodf(__fmul_rn((float)i, PHI_F), TWOPI_F), KSCALE);
    }
    {
        const int* row = ids + (size_t)batch * SEQ;
        int* st = s_tok + sub * SEQ;
        for (int i = d; i < SEQ; i += 64) st[i] = row[i];
    }
    __syncthreads();

    const int* st = s_tok + sub * SEQ;

    // ---- prefetch first PF steps of (a, b*K) ----
    float2 pf[PF];
#pragma unroll
    for (int j = 0; j < PF; j++)
        pf[j] = __ldg(&g_A[(size_t)st[j] * D_MODEL + d]);

    float hr = 0.0f, hi = 0.0f;   // h = (cos, sin) of tracked LUT phase

    for (int sb = 0; sb < SEQ; sb += PF) {
#pragma unroll
        for (int j = 0; j < PF; j++) {
            const int s = sb + j;
            const float a  = pf[j].x;
            const float bk = pf[j].y;

            // prefetch step s+PF (wraps harmlessly on the final chunk)
            {
                int sn = (s + PF) & (SEQ - 1);
                pf[j] = __ldg(&g_A[(size_t)st[sn] * D_MODEL + d]);
            }

            float c = __fadd_rn(bk, s_tphiK[s]);       // off critical path

            // ---- critical path ----
            float yr = __fmaf_rn(hr, a, c);            // theta_r in bin units
            float yi = __fmaf_rn(hi, a, c);
            int   br = __float_as_int(__fadd_rd(yr, MAGIC));   // C + floor(yr)
            int   bi = __float_as_int(__fadd_rd(yi, MAGIC));   // C + floor(yi)
            // k = (floor(yr)+floor(yi)) mod 4096, spliced back into a float
            int   kb = ((br + bi) & 4095) | MAGIC_I;   // single LOP3 after IADD3
            float fk = __fsub_rn(__int_as_float(kb), MAGIC);   // (float)k, exact
            float ang = __fmul_rn(fk, STEP_F);         // == table angle step*k

            hr = __cosf(ang);                          // MUFU.COS
            hi = __sinf(ang);                          // MUFU.SIN (parallel)
        }
    }

    // ---- projection: out[b,n] = sum_k h[k]*W[n,k] + bias[n] ----
    float* sh = s_h + sub * 128;
    sh[d] = hr;
    sh[64 + d] = hi;
    __syncthreads();

    float acc0 = 0.0f, acc1 = 0.0f;
    const float* w0 = projW + (size_t)d * 128;
    const float* w1 = projW + (size_t)(d + 64) * 128;
#pragma unroll 8
    for (int kk = 0; kk < 128; kk++) {
        float hk = sh[kk];
        acc0 = __fmaf_rn(hk, __ldg(w0 + kk), acc0);
        acc1 = __fmaf_rn(hk, __ldg(w1 + kk), acc1);
    }
    out[(size_t)batch * 128 + d]      = __fadd_rn(acc0, __ldg(projB + d));
    out[(size_t)batch * 128 + 64 + d] = __fadd_rn(acc1, __ldg(projB + d + 64));
}

extern "C" void kernel_launch(void* const* d_in, const int* in_sizes, int n_in,
                              void* d_out, int out_size)
{
    const int*   ids  = (const int*)d_in[0];     // (256, 4096) int32
    const float* emb  = (const float*)d_in[1];   // (50257, 128) f32
    const float* W    = (const float*)d_in[2];   // (128, 128) f32
    const float* bias = (const float*)d_in[3];   // (128,) f32
    float* out = (float*)d_out;                  // (256, 128) f32

    prep_kernel<<<(VOCAB * D_MODEL + 255) / 256, 256>>>(emb);

    cudaFuncSetAttribute(rin_scan_kernel,
                         cudaFuncAttributeMaxDynamicSharedMemorySize, SM_TOTAL);
    rin_scan_kernel<<<BATCH_N / 2, 128, SM_TOTAL>>>(ids, W, bias, out);
}

// round 11
// speedup vs baseline: 1.6624x; 1.0828x over previous
#include <cuda_runtime.h>
#include <math.h>

#define D_MODEL   64
#define SEQ       4096
#define BATCH_N   256
#define VOCAB     50257
#define PF        8

#define TWOPI_F   6.2831853071795864769f
#define PHI_F     1.6180339887498948482f
#define STEP_F    ((float)(6.283185307179586 / 4096.0))   /* table angle step */
#define KSCALE    651.8986469044033f                      /* 4096 / (2*pi) */
#define MAGIC     12582912.0f                             /* 2^23 + 2^22 */

// Precomputed per-(token, d): (KSCALE/(1+|w|), b*KSCALE), interleaved for LDG.64
__device__ float2 g_A[(size_t)VOCAB * D_MODEL];

__global__ void __launch_bounds__(256)
prep_kernel(const float* __restrict__ emb)
{
    int idx = blockIdx.x * 256 + threadIdx.x;
    if (idx >= VOCAB * D_MODEL) return;
    int tok = idx >> 6;
    int d   = idx & 63;
    float w = emb[(size_t)tok * 128 + d];
    float b = emb[(size_t)tok * 128 + 64 + d];
    float a = __fdividef(KSCALE, __fadd_rn(1.0f, fabsf(w)));
    g_A[idx] = make_float2(a, __fmul_rn(b, KSCALE));
}

// smem: tok[2][4096] 32KB | tphiK[4096] 16KB | h[2][128] 1KB
#define SM_TOK_OFF   0
#define SM_TPHI_OFF  32768
#define SM_H_OFF     49152
#define SM_TOTAL     50176

__global__ void __launch_bounds__(128, 1)
rin_scan_kernel(const int* __restrict__ ids,
                const float* __restrict__ projW,
                const float* __restrict__ projB,
                float* __restrict__ out)
{
    extern __shared__ unsigned char smem[];
    int*    s_tok   = (int*)  (smem + SM_TOK_OFF);    // [2][4096]
    float*  s_tphiK = (float*)(smem + SM_TPHI_OFF);   // [4096], shared by both subs
    float*  s_h     = (float*)(smem + SM_H_OFF);      // [2][128]

    const int tid = threadIdx.x;
    const int sub = tid >> 6;
    const int d   = tid & 63;
    const int batch = blockIdx.x * 2 + sub;

    // ---- init ----
    for (int i = tid; i < SEQ; i += 128) {
        s_tphiK[i] = __fmul_rn(fmodf(__fmul_rn((float)i, PHI_F), TWOPI_F), KSCALE);
    }
    {
        const int* row = ids + (size_t)batch * SEQ;
        int* st = s_tok + sub * SEQ;
        for (int i = d; i < SEQ; i += 64) st[i] = row[i];
    }
    __syncthreads();

    const int* st = s_tok + sub * SEQ;

    // ---- prologue: stage block 0 coefficients directly ----
    float a_cur[PF], c_cur[PF];
#pragma unroll
    for (int j = 0; j < PF; j++) {
        float2 e = __ldg(&g_A[(size_t)st[j] * D_MODEL + d]);
        a_cur[j] = e.x;
        c_cur[j] = __fadd_rn(e.y, s_tphiK[j]);
    }

    float hr = 0.0f, hi = 0.0f;   // h = (cos, sin) of tracked LUT phase

    for (int sb = 0; sb < SEQ; sb += PF) {
        // ---- stage next block's data (loads issued up-front, off the chain) ----
        const int sn = (sb + PF) & (SEQ - 1);
        float2 pfn[PF];
        float  tphn[PF];
#pragma unroll
        for (int j = 0; j < PF; j++) {
            tphn[j] = s_tphiK[sn + j];
            pfn[j]  = __ldg(&g_A[(size_t)st[sn + j] * D_MODEL + d]);
        }

        // ---- pure-chain inner steps: no memory ops, c pre-added ----
#pragma unroll
        for (int j = 0; j < PF; j++) {
            float yr = __fmaf_rn(hr, a_cur[j], c_cur[j]);       // theta_r in bins
            float yi = __fmaf_rn(hi, a_cur[j], c_cur[j]);
            float fr = __fsub_rn(__fadd_rd(yr, MAGIC), MAGIC);  // floor(yr), exact
            float fi = __fsub_rn(__fadd_rd(yi, MAGIC), MAGIC);  // floor(yi), exact
            float s2 = __fadd_rn(fr, fi);                       // integer-valued, exact
            float ang = __fmul_rn(s2, STEP_F);                  // sin period absorbs mod 4096
            hr = __cosf(ang);                                   // MUFU.COS
            hi = __sinf(ang);                                   // MUFU.SIN (parallel)
        }

        // ---- commit next block's coefficients ----
#pragma unroll
        for (int j = 0; j < PF; j++) {
            a_cur[j] = pfn[j].x;
            c_cur[j] = __fadd_rn(pfn[j].y, tphn[j]);
        }
    }

    // ---- projection: out[b,n] = sum_k h[k]*W[n,k] + bias[n] ----
    float* sh = s_h + sub * 128;
    sh[d] = hr;
    sh[64 + d] = hi;
    __syncthreads();

    float acc0 = 0.0f, acc1 = 0.0f;
    const float* w0 = projW + (size_t)d * 128;
    const float* w1 = projW + (size_t)(d + 64) * 128;
#pragma unroll 8
    for (int kk = 0; kk < 128; kk++) {
        float hk = sh[kk];
        acc0 = __fmaf_rn(hk, __ldg(w0 + kk), acc0);
        acc1 = __fmaf_rn(hk, __ldg(w1 + kk), acc1);
    }
    out[(size_t)batch * 128 + d]      = __fadd_rn(acc0, __ldg(projB + d));
    out[(size_t)batch * 128 + 64 + d] = __fadd_rn(acc1, __ldg(projB + d + 64));
}

extern "C" void kernel_launch(void* const* d_in, const int* in_sizes, int n_in,
                              void* d_out, int out_size)
{
    const int*   ids  = (const int*)d_in[0];     // (256, 4096) int32
    const float* emb  = (const float*)d_in[1];   // (50257, 128) f32
    const float* W    = (const float*)d_in[2];   // (128, 128) f32
    const float* bias = (const float*)d_in[3];   // (128,) f32
    float* out = (float*)d_out;                  // (256, 128) f32

    prep_kernel<<<(VOCAB * D_MODEL + 255) / 256, 256>>>(emb);

    cudaFuncSetAttribute(rin_scan_kernel,
                         cudaFuncAttributeMaxDynamicSharedMemorySize, SM_TOTAL);
    rin_scan_kernel<<<BATCH_N / 2, 128, SM_TOTAL>>>(ids, W, bias, out);
}